// round 2
// baseline (speedup 1.0000x reference)
#include <cuda_runtime.h>

typedef unsigned long long u64;

#define Bsz 256
#define Lsz 500
#define Hsz 512
#define Isz 35   // D + C
#define OUTsz 35 // 2*15 + 5

// h activations, transposed for the decoder: [L][H][B]. 262 MB device global.
__device__ float g_h[Lsz * Hsz * Bsz];

// ---- packed f32x2 helpers (sm_103a dual-rate fp32 path) ----
__device__ __forceinline__ u64 fma2(u64 a, u64 b, u64 c) {
    u64 d;
    asm("fma.rn.f32x2 %0, %1, %2, %3;" : "=l"(d) : "l"(a), "l"(b), "l"(c));
    return d;
}
__device__ __forceinline__ u64 add2(u64 a, u64 b) {
    u64 d;
    asm("add.rn.f32x2 %0, %1, %2;" : "=l"(d) : "l"(a), "l"(b));
    return d;
}
__device__ __forceinline__ u64 pack2(float x, float y) {
    u64 r;
    asm("mov.b64 %0, {%1, %2};" : "=l"(r) : "f"(x), "f"(y));
    return r;
}
__device__ __forceinline__ void unpack2(u64 v, float& x, float& y) {
    asm("mov.b64 {%0, %1}, %2;" : "=f"(x), "=f"(y) : "l"(v));
}

// ============================================================
// Kernel 1: fused encoder + exclusive scan + ReLU.
// The recurrence  a[l] = b_enc + sum_{j<l} c[j]  is elementwise in (b,h),
// so each thread owns a (2b x 2h) tile of the scan state and marches l.
// grid: (8 b-tiles of 32, 32 h-tiles of 16), block 128 (16 b-slots x 8 hp).
// f32x2 lanes = the b-pair; w is lane-duplicated.
// Writes g_h[l][h][b] (coalesced float2 stores).
// ============================================================
__global__ void __launch_bounds__(128) fused_enc_scan(
    const float* __restrict__ inputs,  // [B, L, 3]
    const float* __restrict__ z,       // [B, L, 32]
    const float* __restrict__ W,       // [L, 35, 512]
    const float* __restrict__ benc)    // [1, 512]
{
    const int bx = blockIdx.x;          // b-tile (32 b)
    const int by = blockIdx.y;          // h-tile (16 h)
    const int t  = threadIdx.x;
    const int bs = t & 15;              // b-pair slot
    const int hp = t >> 4;              // h-pair slot (0..7)

    __shared__ u64 xs2[Isz][16];        // x pairs: {x[b0], x[b1]} per (i, slot)
    __shared__ u64 ws2[Isz][16];        // w duplicated: {w,w} per (i, h)

    const int b0 = bx * 32 + 2 * bs;
    const int h0 = by * 16 + 2 * hp;

    const float be0 = benc[h0];
    const float be1 = benc[h0 + 1];
    const u64 be2_0 = pack2(be0, be0);
    const u64 be2_1 = pack2(be1, be1);

    u64 acc0 = 0ULL, acc1 = 0ULL;       // running prefix for h0, h0+1 (b-pair lanes)

    for (int l = 0; l < Lsz; l++) {
        __syncthreads();
        // stage x pairs: 560 entries
        for (int idx = t; idx < 16 * Isz; idx += 128) {
            int s = idx / Isz, i = idx % Isz;
            int bg = bx * 32 + 2 * s;
            float v0, v1;
            if (i < 3) {
                v0 = inputs[(bg * Lsz + l) * 3 + i];
                v1 = inputs[((bg + 1) * Lsz + l) * 3 + i];
            } else {
                v0 = z[(bg * Lsz + l) * 32 + (i - 3)];
                v1 = z[((bg + 1) * Lsz + l) * 32 + (i - 3)];
            }
            xs2[i][s] = pack2(v0, v1);
        }
        // stage w duplicated: 560 entries, coalesced over h
        for (int idx = t; idx < 16 * Isz; idx += 128) {
            int i = idx >> 4, hh = idx & 15;
            float w = W[(l * Isz + i) * Hsz + by * 16 + hh];
            ws2[i][hh] = pack2(w, w);
        }
        __syncthreads();

        // c = x @ W for this l; 4 independent chains for ILP
        u64 c0a = 0ULL, c0b = 0ULL, c1a = 0ULL, c1b = 0ULL;
#pragma unroll
        for (int i = 0; i < Isz; i += 2) {
            u64 x2 = xs2[i][bs];
            c0a = fma2(x2, ws2[i][2 * hp], c0a);
            c1a = fma2(x2, ws2[i][2 * hp + 1], c1a);
            if (i + 1 < Isz) {
                u64 x2b = xs2[i + 1][bs];
                c0b = fma2(x2b, ws2[i + 1][2 * hp], c0b);
                c1b = fma2(x2b, ws2[i + 1][2 * hp + 1], c1b);
            }
        }
        u64 c0 = add2(c0a, c0b);
        u64 c1 = add2(c1a, c1b);

        // exclusive: emit h from acc BEFORE adding c[l]
        {
            u64 a = add2(acc0, be2_0);
            float lo, hi; unpack2(a, lo, hi);
            float2 o; o.x = fmaxf(lo, 0.f); o.y = fmaxf(hi, 0.f);
            *reinterpret_cast<float2*>(&g_h[(l * Hsz + h0) * Bsz + b0]) = o;
        }
        {
            u64 a = add2(acc1, be2_1);
            float lo, hi; unpack2(a, lo, hi);
            float2 o; o.x = fmaxf(lo, 0.f); o.y = fmaxf(hi, 0.f);
            *reinterpret_cast<float2*>(&g_h[(l * Hsz + h0 + 1) * Bsz + b0]) = o;
        }
        acc0 = add2(acc0, c0);
        acc1 = add2(acc1, c1);
    }
}

// ============================================================
// Kernel 2: decoder. out[b,l,o] = sum_h h[l,h,b] * V[l,h,o] + bias.
// One block per l; thread = b-pair (f32x2 lanes). V staged dup-packed in
// smem (broadcast LDS.64); h read as coalesced LDG.64 from g_h[l][kk][2t].
// Inner loop per kk: 1 LDG.64 + 35 LDS.64 + 35 fma2 -> fma2-issue bound.
// ============================================================
__global__ void __launch_bounds__(128) dec_kernel(
    const float* __restrict__ Vmu,   // [L, 512, 15]
    const float* __restrict__ bmu,   // [L, 1, 15]
    const float* __restrict__ Vsig,  // [L, 512, 15]
    const float* __restrict__ bsig,  // [L, 1, 15]
    const float* __restrict__ Vpi,   // [L, 512, 5]
    const float* __restrict__ bpi,   // [L, 1, 5]
    float* __restrict__ out)         // [B, L, 35]
{
    const int l = blockIdx.x;
    const int t = threadIdx.x;       // b-pair: b0 = 2t, b1 = 2t+1

    __shared__ u64 vs2[128][OUTsz];  // dup-packed V chunk, 35.8 KB

    u64 acc[OUTsz];
#pragma unroll
    for (int o = 0; o < OUTsz; o++) acc[o] = 0ULL;

    for (int k0 = 0; k0 < Hsz; k0 += 128) {
        __syncthreads();
        {
            const float* vm = Vmu + (l * Hsz + k0) * 15;
            for (int j = t; j < 128 * 15; j += 128) {
                int kk = j / 15, o = j % 15;
                float v = vm[j];
                vs2[kk][o] = pack2(v, v);
            }
            const float* vg = Vsig + (l * Hsz + k0) * 15;
            for (int j = t; j < 128 * 15; j += 128) {
                int kk = j / 15, o = j % 15;
                float v = vg[j];
                vs2[kk][15 + o] = pack2(v, v);
            }
            const float* vp = Vpi + (l * Hsz + k0) * 5;
            for (int j = t; j < 128 * 5; j += 128) {
                int kk = j / 5, m = j % 5;
                float v = vp[j];
                vs2[kk][30 + m] = pack2(v, v);
            }
        }
        __syncthreads();

        const float* hrow = &g_h[((size_t)l * Hsz + k0) * Bsz + 2 * t];
#pragma unroll 4
        for (int kk = 0; kk < 128; kk++) {
            float2 hv = *reinterpret_cast<const float2*>(hrow + (size_t)kk * Bsz);
            u64 h2 = pack2(hv.x, hv.y);
#pragma unroll
            for (int o = 0; o < OUTsz; o++)
                acc[o] = fma2(h2, vs2[kk][o], acc[o]);
        }
    }

    // bias + store (both b rows)
    const int b0 = 2 * t;
    float* o0 = &out[((size_t)b0 * Lsz + l) * OUTsz];
    float* o1 = &out[((size_t)(b0 + 1) * Lsz + l) * OUTsz];
#pragma unroll
    for (int o = 0; o < OUTsz; o++) {
        float bv = (o < 15) ? bmu[l * 15 + o]
                 : (o < 30) ? bsig[l * 15 + (o - 15)]
                            : bpi[l * 5 + (o - 30)];
        float lo, hi; unpack2(acc[o], lo, hi);
        o0[o] = lo + bv;
        o1[o] = hi + bv;
    }
}

extern "C" void kernel_launch(void* const* d_in, const int* in_sizes, int n_in,
                              void* d_out, int out_size) {
    (void)in_sizes; (void)n_in; (void)out_size;
    const float* inputs = (const float*)d_in[0];
    const float* z      = (const float*)d_in[1];
    const float* W_enc  = (const float*)d_in[2];
    const float* b_enc  = (const float*)d_in[3];
    const float* V_mu   = (const float*)d_in[4];
    const float* b_mu   = (const float*)d_in[5];
    const float* V_sig  = (const float*)d_in[6];
    const float* b_sig  = (const float*)d_in[7];
    const float* V_pi   = (const float*)d_in[8];
    const float* b_pi   = (const float*)d_in[9];
    float* out = (float*)d_out;

    fused_enc_scan<<<dim3(8, 32), 128>>>(inputs, z, W_enc, b_enc);
    dec_kernel<<<Lsz, 128>>>(V_mu, b_mu, V_sig, b_sig, V_pi, b_pi, out);
}

// round 3
// speedup vs baseline: 4.9366x; 4.9366x over previous
#include <cuda_runtime.h>

typedef unsigned long long u64;

#define Bsz 256
#define Lsz 500
#define Hsz 512
#define Isz 35
#define OUTsz 35

// Single scratch buffer: encoder writes c[l][b][h]; scan converts IN-PLACE to
// h[l][b][h] = relu(b_enc + exclusive_prefix); decoder reads it. 262 MB.
__device__ float g_c[(size_t)Lsz * Bsz * Hsz];

// ---- packed f32x2 helpers ----
__device__ __forceinline__ u64 fma2(u64 a, u64 b, u64 c) {
    u64 d;
    asm("fma.rn.f32x2 %0, %1, %2, %3;" : "=l"(d) : "l"(a), "l"(b), "l"(c));
    return d;
}
__device__ __forceinline__ u64 pack2(float x, float y) {
    u64 r;
    asm("mov.b64 %0, {%1, %2};" : "=l"(r) : "f"(x), "f"(y));
    return r;
}
__device__ __forceinline__ void unpack2(u64 v, float& x, float& y) {
    asm("mov.b64 {%0, %1}, %2;" : "=f"(x), "=f"(y) : "l"(v));
}

// ============================================================
// Kernel 1: encoder. c[l][b][h] = sum_i x[l,b,i] * W[l,i,h]
// grid (hq=4, bq=4, l=500), block 256. Thread tile: 4 b x 4 h-pairs.
// f32x2 lanes = h-pair (native from W); x pre-duplicated in smem.
// Inner iter: 4 LDS.64 x-dup + 4 LDS.64 w + 16 fma2  (ratio 1.5).
// ============================================================
__global__ void __launch_bounds__(256) enc_kernel(
    const float* __restrict__ inputs,  // [B, L, 3]
    const float* __restrict__ z,       // [B, L, 32]
    const float* __restrict__ W)       // [L, 35, 512]
{
    const int hq = blockIdx.x;   // h quarter (128 h)
    const int bq = blockIdx.y;   // b quarter (64 b)
    const int l  = blockIdx.z;
    const int t  = threadIdx.x;
    const int ht = t & 15;       // h-pair thread
    const int bt = t >> 4;       // b thread

    __shared__ u64   xs[Isz][64];    // x duplicated into both lanes
    __shared__ float ws[Isz][128];   // w scalar; h-pairs read as LDS.64

    // stage x (dup-packed): 64 b x 35 i
    for (int idx = t; idx < 64 * Isz; idx += 256) {
        int bl = idx / Isz, i = idx - bl * Isz;
        int b = bq * 64 + bl;
        float v = (i < 3) ? inputs[(b * Lsz + l) * 3 + i]
                          : z[(b * Lsz + l) * 32 + (i - 3)];
        xs[i][bl] = pack2(v, v);
    }
    // stage w: 35 i x 128 h (coalesced)
    for (int idx = t; idx < Isz * 128; idx += 256) {
        int i = idx >> 7, hh = idx & 127;
        ws[i][hh] = W[(l * Isz + i) * Hsz + hq * 128 + hh];
    }
    __syncthreads();

    u64 acc[4][4];
#pragma unroll
    for (int ii = 0; ii < 4; ii++)
#pragma unroll
        for (int jj = 0; jj < 4; jj++) acc[ii][jj] = 0ULL;

#pragma unroll
    for (int i = 0; i < Isz; i++) {
        u64 xv[4], wv[4];
#pragma unroll
        for (int ii = 0; ii < 4; ii++) xv[ii] = xs[i][bt + 16 * ii];
#pragma unroll
        for (int jj = 0; jj < 4; jj++)
            wv[jj] = *reinterpret_cast<const u64*>(&ws[i][2 * (ht + 16 * jj)]);
#pragma unroll
        for (int ii = 0; ii < 4; ii++)
#pragma unroll
            for (int jj = 0; jj < 4; jj++)
                acc[ii][jj] = fma2(xv[ii], wv[jj], acc[ii][jj]);
    }

    // store c[l][b][h]: coalesced STG.64 across ht lanes
#pragma unroll
    for (int ii = 0; ii < 4; ii++) {
        size_t row = ((size_t)l * Bsz + bq * 64 + bt + 16 * ii) * Hsz + hq * 128;
#pragma unroll
        for (int jj = 0; jj < 4; jj++)
            *reinterpret_cast<u64*>(&g_c[row + 2 * (ht + 16 * jj)]) = acc[ii][jj];
    }
}

// ============================================================
// Kernel 2: in-place exclusive scan over l + b_enc + ReLU.
// Thread owns an (b, h-pair) column; pure streaming, 65536 threads.
// ============================================================
__global__ void __launch_bounds__(128) scan_kernel(
    const float* __restrict__ benc)    // [1, 512]
{
    const int g = blockIdx.x * 128 + threadIdx.x;   // 0..65535
    const int b = g >> 8;
    const int hp = g & 255;

    float2 be = *reinterpret_cast<const float2*>(&benc[2 * hp]);
    float2* p = reinterpret_cast<float2*>(g_c) + ((size_t)b * Hsz + 2 * hp) / 2;
    const size_t stride = (size_t)Bsz * Hsz / 2;   // float2 stride per l

    float ax = 0.f, ay = 0.f;
#pragma unroll 4
    for (int l = 0; l < Lsz; l++) {
        float2 v = p[l * stride];
        float2 o;
        o.x = fmaxf(ax + be.x, 0.f);
        o.y = fmaxf(ay + be.y, 0.f);
        p[l * stride] = o;
        ax += v.x; ay += v.y;
    }
}

// ============================================================
// Kernel 3: decoder. out[b,l,o] = sum_h h[l,b,h]*V[l,h,o] + bias.
// f32x2 lanes = o-pair (native from V, O padded to 40); h dup-packed
// into smem during staging (no transpose). Thread tile: 4 b x 5 o-pairs.
// grid (l=500, bq=2), block 128 (32 b-thr x 4 o-thr). k-tile 32.
// Inner iter: 4 LDS.64 h + 5 LDS.64 v + 20 fma2  (ratio 1.45).
// ============================================================
__global__ void __launch_bounds__(128) dec_kernel(
    const float* __restrict__ Vmu,   // [L, 512, 15]
    const float* __restrict__ bmu,   // [L, 1, 15]
    const float* __restrict__ Vsig,  // [L, 512, 15]
    const float* __restrict__ bsig,  // [L, 1, 15]
    const float* __restrict__ Vpi,   // [L, 512, 5]
    const float* __restrict__ bpi,   // [L, 1, 5]
    float* __restrict__ out)         // [B, L, 35]
{
    const int l  = blockIdx.x;
    const int bq = blockIdx.y;       // b half (128 b)
    const int t  = threadIdx.x;
    const int ot = t & 3;            // o-pair thread (x5 -> 20 op = 40 o)
    const int bt = t >> 2;           // b thread (x4 -> 128 b)

    __shared__ u64   hs[128][33];    // h dup-packed, [b][kk], pad
    __shared__ float vs[32][40];     // V combined (mu|sig|pi|pad), scalar

    // zero the o-padding once
    for (int idx = t; idx < 32 * 5; idx += 128)
        vs[idx / 5][35 + idx % 5] = 0.f;

    u64 acc[4][5];
#pragma unroll
    for (int ib = 0; ib < 4; ib++)
#pragma unroll
        for (int jo = 0; jo < 5; jo++) acc[ib][jo] = 0ULL;

    for (int k0 = 0; k0 < Hsz; k0 += 32) {
        __syncthreads();
        // stage h: 128 b x 32 kk, coalesced float4 reads, dup-pack
        for (int idx = t; idx < 128 * 8; idx += 128) {
            int bl = idx >> 3, kf = idx & 7;
            const float4 v = *reinterpret_cast<const float4*>(
                &g_c[((size_t)l * Bsz + bq * 128 + bl) * Hsz + k0 + 4 * kf]);
            hs[bl][4 * kf + 0] = pack2(v.x, v.x);
            hs[bl][4 * kf + 1] = pack2(v.y, v.y);
            hs[bl][4 * kf + 2] = pack2(v.z, v.z);
            hs[bl][4 * kf + 3] = pack2(v.w, v.w);
        }
        // stage V (all three blocks are (kk,o)-contiguous in gmem)
        {
            const float* vm = Vmu + ((size_t)l * Hsz + k0) * 15;
            for (int idx = t; idx < 32 * 15; idx += 128)
                vs[idx / 15][idx % 15] = vm[idx];
            const float* vg = Vsig + ((size_t)l * Hsz + k0) * 15;
            for (int idx = t; idx < 32 * 15; idx += 128)
                vs[idx / 15][15 + idx % 15] = vg[idx];
            const float* vp = Vpi + ((size_t)l * Hsz + k0) * 5;
            for (int idx = t; idx < 32 * 5; idx += 128)
                vs[idx / 5][30 + idx % 5] = vp[idx];
        }
        __syncthreads();

#pragma unroll 4
        for (int kk = 0; kk < 32; kk++) {
            u64 hv[4], vv[5];
#pragma unroll
            for (int ib = 0; ib < 4; ib++) hv[ib] = hs[bt + 32 * ib][kk];
#pragma unroll
            for (int jo = 0; jo < 5; jo++)
                vv[jo] = *reinterpret_cast<const u64*>(&vs[kk][2 * (ot + 4 * jo)]);
#pragma unroll
            for (int ib = 0; ib < 4; ib++)
#pragma unroll
                for (int jo = 0; jo < 5; jo++)
                    acc[ib][jo] = fma2(hv[ib], vv[jo], acc[ib][jo]);
        }
    }

    // bias + store (skip o >= 35 padding)
#pragma unroll
    for (int ib = 0; ib < 4; ib++) {
        int b = bq * 128 + bt + 32 * ib;
        float* op = &out[((size_t)b * Lsz + l) * OUTsz];
#pragma unroll
        for (int jo = 0; jo < 5; jo++) {
            int o0 = 2 * (ot + 4 * jo);
            float lo, hi;
            unpack2(acc[ib][jo], lo, hi);
#pragma unroll
            for (int s = 0; s < 2; s++) {
                int o = o0 + s;
                if (o < OUTsz) {
                    float bv = (o < 15) ? bmu[l * 15 + o]
                             : (o < 30) ? bsig[l * 15 + (o - 15)]
                                        : bpi[l * 5 + (o - 30)];
                    op[o] = (s == 0 ? lo : hi) + bv;
                }
            }
        }
    }
}

extern "C" void kernel_launch(void* const* d_in, const int* in_sizes, int n_in,
                              void* d_out, int out_size) {
    (void)in_sizes; (void)n_in; (void)out_size;
    const float* inputs = (const float*)d_in[0];
    const float* z      = (const float*)d_in[1];
    const float* W_enc  = (const float*)d_in[2];
    const float* b_enc  = (const float*)d_in[3];
    const float* V_mu   = (const float*)d_in[4];
    const float* b_mu   = (const float*)d_in[5];
    const float* V_sig  = (const float*)d_in[6];
    const float* b_sig  = (const float*)d_in[7];
    const float* V_pi   = (const float*)d_in[8];
    const float* b_pi   = (const float*)d_in[9];
    float* out = (float*)d_out;

    enc_kernel<<<dim3(4, 4, Lsz), 256>>>(inputs, z, W_enc);
    scan_kernel<<<(Bsz * Hsz / 2) / 128, 128>>>(b_enc);
    dec_kernel<<<dim3(Lsz, 2), 128>>>(V_mu, b_mu, V_sig, b_sig, V_pi, b_pi, out);
}

// round 4
// speedup vs baseline: 5.2032x; 1.0540x over previous
#include <cuda_runtime.h>

typedef unsigned long long u64;

#define Bsz 256
#define Lsz 500
#define Hsz 512
#define Isz 35
#define OUTsz 35

// Scratch: encoder writes c[l][b][h]; scan converts IN-PLACE to
// h[l][b][h] = relu(b_enc + exclusive prefix); decoder reads it. 262 MB.
__device__ float g_c[(size_t)Lsz * Bsz * Hsz];

// ---- packed f32x2 helpers ----
__device__ __forceinline__ u64 fma2(u64 a, u64 b, u64 c) {
    u64 d;
    asm("fma.rn.f32x2 %0, %1, %2, %3;" : "=l"(d) : "l"(a), "l"(b), "l"(c));
    return d;
}
__device__ __forceinline__ u64 pack2(float x, float y) {
    u64 r;
    asm("mov.b64 %0, {%1, %2};" : "=l"(r) : "f"(x), "f"(y));
    return r;
}
__device__ __forceinline__ void unpack2(u64 v, float& x, float& y) {
    asm("mov.b64 {%0, %1}, %2;" : "=f"(x), "=f"(y) : "l"(v));
}

// ============================================================
// Kernel 1: encoder. c[l][b][h] = sum_i x[l,b,i] * W[l,i,h]
// grid (hx=2, bq=8, l=500), block 128 (16 ht x 8 bt).
// Thread tile: 4 b x 8 h-pairs -> 32 fma2 : 10 LDS per i.
// Lanes = h-pair (native from W); x dup-packed in smem.
// Epilogue bounces c through smem for coalesced float4 stores.
// ============================================================
__global__ void __launch_bounds__(128, 4) enc_kernel(
    const float* __restrict__ inputs,  // [B, L, 3]
    const float* __restrict__ z,       // [B, L, 32]
    const float* __restrict__ W)       // [L, 35, 512]
{
    const int hx = blockIdx.x;   // h half (256 h)
    const int bq = blockIdx.y;   // b tile (32 b)
    const int l  = blockIdx.z;
    const int t  = threadIdx.x;
    const int ht = t & 15;       // h-pair thread (pairs strided by 16)
    const int bt = t >> 4;       // b thread (4 consecutive b)

    __shared__ __align__(16) u64   xs[Isz][32];   // x dup-packed per b
    __shared__ __align__(16) float ws[Isz][256];  // w scalar

    // stage x (dup-packed): 32 b x 35 i  (i fastest -> coalesced)
    for (int idx = t; idx < 32 * Isz; idx += 128) {
        int s = idx / Isz, i = idx - s * Isz;
        int b = bq * 32 + s;
        float v = (i < 3) ? inputs[(b * Lsz + l) * 3 + i]
                          : z[(b * Lsz + l) * 32 + (i - 3)];
        xs[i][s] = pack2(v, v);
    }
    // stage w: 35 i x 256 h (coalesced)
    for (int idx = t; idx < Isz * 256; idx += 128) {
        int i = idx >> 8, hh = idx & 255;
        ws[i][hh] = W[(l * Isz + i) * Hsz + hx * 256 + hh];
    }
    __syncthreads();

    u64 acc[4][8];
#pragma unroll
    for (int ii = 0; ii < 4; ii++)
#pragma unroll
        for (int j = 0; j < 8; j++) acc[ii][j] = 0ULL;

#pragma unroll
    for (int i = 0; i < Isz; i++) {
        ulonglong2 xa = *reinterpret_cast<const ulonglong2*>(&xs[i][4 * bt]);
        ulonglong2 xb = *reinterpret_cast<const ulonglong2*>(&xs[i][4 * bt + 2]);
        u64 xv[4] = {xa.x, xa.y, xb.x, xb.y};
        u64 wv[8];
#pragma unroll
        for (int j = 0; j < 8; j++)
            wv[j] = *reinterpret_cast<const u64*>(&ws[i][2 * (ht + 16 * j)]);
#pragma unroll
        for (int ii = 0; ii < 4; ii++)
#pragma unroll
            for (int j = 0; j < 8; j++)
                acc[ii][j] = fma2(xv[ii], wv[j], acc[ii][j]);
    }

    // Epilogue: bounce through smem (reuse ws) for coalesced stores.
    __syncthreads();                       // everyone done reading ws
    u64* cbuf = reinterpret_cast<u64*>(&ws[0][0]);   // [32 b][128 h-pairs]
#pragma unroll
    for (int ii = 0; ii < 4; ii++)
#pragma unroll
        for (int j = 0; j < 8; j++)
            cbuf[(4 * bt + ii) * 128 + ht + 16 * j] = acc[ii][j];
    __syncthreads();

    const float* cf = reinterpret_cast<const float*>(cbuf);
#pragma unroll
    for (int n = 0; n < 16; n++) {
        int f = t + 128 * n;               // float4 index, 2048 total
        int bl = f >> 6, c4 = f & 63;
        float4 v = *reinterpret_cast<const float4*>(&cf[bl * 256 + 4 * c4]);
        *reinterpret_cast<float4*>(
            &g_c[((size_t)l * Bsz + bq * 32 + bl) * Hsz + hx * 256 + 4 * c4]) = v;
    }
}

// ============================================================
// Kernel 2: in-place exclusive scan over l + b_enc + ReLU.
// ============================================================
__global__ void __launch_bounds__(128) scan_kernel(
    const float* __restrict__ benc)    // [1, 512]
{
    const int g = blockIdx.x * 128 + threadIdx.x;   // 0..65535
    const int b = g >> 8;
    const int hp = g & 255;

    float2 be = *reinterpret_cast<const float2*>(&benc[2 * hp]);
    float2* p = reinterpret_cast<float2*>(g_c) + ((size_t)b * Hsz) / 2 + hp;
    const size_t stride = (size_t)Bsz * Hsz / 2;

    float ax = 0.f, ay = 0.f;
#pragma unroll 4
    for (int l = 0; l < Lsz; l++) {
        float2 v = p[l * stride];
        float2 o;
        o.x = fmaxf(ax + be.x, 0.f);
        o.y = fmaxf(ay + be.y, 0.f);
        p[l * stride] = o;
        ax += v.x; ay += v.y;
    }
}

// ============================================================
// Kernel 3: decoder with f32x2 lanes on K (k-pairs).
// out[b,l,o] = sum_k h[l,b,k]*V[l,k,o] + bias.
// grid (l=500, bq=2), block 128 (32 bt x 4 ot).
// Thread tile: 4 b x 10 o -> 40 fma2 : 9 LDS per k-pair.
// hs staged as raw copy of g_c rows; V packed to k-pairs at staging.
// O padded to 40; cols 35..39 computed on garbage, never stored.
// ============================================================
__global__ void __launch_bounds__(128, 4) dec_kernel(
    const float* __restrict__ Vmu,   // [L, 512, 15]
    const float* __restrict__ bmu,   // [L, 1, 15]
    const float* __restrict__ Vsig,  // [L, 512, 15]
    const float* __restrict__ bsig,  // [L, 1, 15]
    const float* __restrict__ Vpi,   // [L, 512, 5]
    const float* __restrict__ bpi,   // [L, 1, 5]
    float* __restrict__ out)         // [B, L, 35]
{
    const int l  = blockIdx.x;
    const int bq = blockIdx.y;       // b half (128 b)
    const int t  = threadIdx.x;
    const int ot = t & 3;            // o group: 10 consecutive o
    const int bt = t >> 2;           // b group: 4 consecutive b

    __shared__ __align__(16) u64 hs[128][33];   // h k-pairs per b (pad->2-way max)
    __shared__ __align__(16) u64 vs2[32][40];   // V k-pairs per o (o padded)

    // bias for this thread's 10 columns
    float bias[10];
#pragma unroll
    for (int j = 0; j < 10; j++) {
        int o = 10 * ot + j;
        bias[j] = (o < 15) ? bmu[l * 15 + o]
                : (o < 30) ? bsig[l * 15 + (o - 15)]
                : (o < 35) ? bpi[l * 5 + (o - 30)] : 0.f;
    }

    u64 acc[4][10];
#pragma unroll
    for (int ii = 0; ii < 4; ii++)
#pragma unroll
        for (int j = 0; j < 10; j++) acc[ii][j] = 0ULL;

    for (int k0 = 0; k0 < Hsz; k0 += 64) {    // 8 k-tiles of 64
        __syncthreads();
        // stage h: raw copy, 128 b x 64 k floats -> k-pairs u64
        for (int n = 0; n < 16; n++) {
            int f = t + 128 * n;              // float4 idx, 2048 total
            int bl = f >> 4, kq = f & 15;
            float4 v = *reinterpret_cast<const float4*>(
                &g_c[((size_t)l * Bsz + bq * 128 + bl) * Hsz + k0 + 4 * kq]);
            hs[bl][2 * kq]     = pack2(v.x, v.y);
            hs[bl][2 * kq + 1] = pack2(v.z, v.w);
        }
        // stage V k-pairs: vs2[kkp][o] = {V[k0+2kkp][o], V[k0+2kkp+1][o]}
        {
            const float* vm = Vmu + ((size_t)l * Hsz + k0) * 15;
            for (int idx = t; idx < 32 * 15; idx += 128) {
                int kkp = idx / 15, o = idx - kkp * 15;
                vs2[kkp][o] = pack2(vm[kkp * 30 + o], vm[kkp * 30 + 15 + o]);
            }
            const float* vg = Vsig + ((size_t)l * Hsz + k0) * 15;
            for (int idx = t; idx < 32 * 15; idx += 128) {
                int kkp = idx / 15, o = idx - kkp * 15;
                vs2[kkp][15 + o] = pack2(vg[kkp * 30 + o], vg[kkp * 30 + 15 + o]);
            }
            const float* vp = Vpi + ((size_t)l * Hsz + k0) * 5;
            for (int idx = t; idx < 32 * 5; idx += 128) {
                int kkp = idx / 5, o = idx - kkp * 5;
                vs2[kkp][30 + o] = pack2(vp[kkp * 10 + o], vp[kkp * 10 + 5 + o]);
            }
        }
        __syncthreads();

#pragma unroll
        for (int kkp = 0; kkp < 32; kkp++) {
            u64 hv[4];
#pragma unroll
            for (int ii = 0; ii < 4; ii++) hv[ii] = hs[4 * bt + ii][kkp];
            u64 vv[10];
#pragma unroll
            for (int jq = 0; jq < 5; jq++) {
                ulonglong2 vq = *reinterpret_cast<const ulonglong2*>(
                    &vs2[kkp][10 * ot + 2 * jq]);
                vv[2 * jq] = vq.x; vv[2 * jq + 1] = vq.y;
            }
#pragma unroll
            for (int ii = 0; ii < 4; ii++)
#pragma unroll
                for (int j = 0; j < 10; j++)
                    acc[ii][j] = fma2(hv[ii], vv[j], acc[ii][j]);
        }
    }

    // epilogue: horizontal add over the k-pair lanes + bias
#pragma unroll
    for (int ii = 0; ii < 4; ii++) {
        int b = bq * 128 + 4 * bt + ii;
        float* op = &out[((size_t)b * Lsz + l) * OUTsz];
#pragma unroll
        for (int j = 0; j < 10; j++) {
            int o = 10 * ot + j;
            if (o < OUTsz) {
                float lo, hi;
                unpack2(acc[ii][j], lo, hi);
                op[o] = lo + hi + bias[j];
            }
        }
    }
}

extern "C" void kernel_launch(void* const* d_in, const int* in_sizes, int n_in,
                              void* d_out, int out_size) {
    (void)in_sizes; (void)n_in; (void)out_size;
    const float* inputs = (const float*)d_in[0];
    const float* z      = (const float*)d_in[1];
    const float* W_enc  = (const float*)d_in[2];
    const float* b_enc  = (const float*)d_in[3];
    const float* V_mu   = (const float*)d_in[4];
    const float* b_mu   = (const float*)d_in[5];
    const float* V_sig  = (const float*)d_in[6];
    const float* b_sig  = (const float*)d_in[7];
    const float* V_pi   = (const float*)d_in[8];
    const float* b_pi   = (const float*)d_in[9];
    float* out = (float*)d_out;

    enc_kernel<<<dim3(2, 8, Lsz), 128>>>(inputs, z, W_enc);
    scan_kernel<<<(Bsz * Hsz / 2) / 128, 128>>>(b_enc);
    dec_kernel<<<dim3(Lsz, 2), 128>>>(V_mu, b_mu, V_sig, b_sig, V_pi, b_pi, out);
}